// round 13
// baseline (speedup 1.0000x reference)
#include <cuda_runtime.h>
#include <math.h>

// Shapes fixed by setup_inputs(): B=64, S=256, H=768, D=64, NEG=4
// Inputs: encoded[B,S,H] f32, n_encoded[B*NEG,S,H] f32,
//         mask1[B,S,1], mask2[B,S,1], mask_u_neg[B*NEG,S,1], W[D,H]
// Output: scalar float loss.
//
// Grid = 64 (one block per batch; R6 structure = measured best), with the
// chain shortened: x streamed from global inside the matvec (no gather
// phase), expmap0 sum-of-squares fused into pass 0, acc[2][6] x 4 passes
// (regs ~150, no spills), in-smem epilogue (no global round trip), fast
// __expf/__logf-based transcendentals on the tail, and last-block mean
// reduction instead of a memset node. Counters self-reset for graph replay.

#define PB_EPS 1e-15f
#define PB_BND (1.0f - 1e-7f)

#define PB_B   64
#define PB_S   256
#define PB_H   768
#define PB_D   64
#define PB_NEG 4
#define PB_H16 (PB_H / 4)   // 192 16-byte chunks per row

typedef unsigned long long u64;

__device__ float        g_part[PB_B];
__device__ unsigned int g_cnt;          // zero-init; reset by final block

__device__ __forceinline__ float warp_sum(float v) {
#pragma unroll
    for (int o = 16; o; o >>= 1) v += __shfl_xor_sync(0xffffffffu, v, o);
    return v;
}

// packed dual-fp32 FMA (Blackwell f32x2; exact 2x IEEE fmaf)
__device__ __forceinline__ void fma_x2(u64& d, u64 a, u64 b, u64 c) {
    asm("fma.rn.f32x2 %0, %1, %2, %3;" : "=l"(d) : "l"(a), "l"(b), "l"(c));
}

__device__ __forceinline__ float x2_hsum(u64 a) {
    float2 f = *reinterpret_cast<float2*>(&a);
    return f.x + f.y;
}

// fast artanh for x in [0, BND]: 0.5*log((1+x)/(1-x)); relerr ~1e-7,
// far inside the 1e-3 budget.
__device__ __forceinline__ float atanh_fast(float x) {
    return 0.5f * __logf((1.f + x) / (1.f - x));
}

// 2 * artanh(|| mobius_add(-u, w) ||), vectors split 2 elems/lane (D=64).
__device__ __forceinline__ float pb_dist(
    float u0, float u1, float w0, float w1, float x2, float y2, float duw)
{
    float xy  = -duw;
    float ca  = 1.f + 2.f * xy + y2;   // coefficient of (-u)
    float cb  = 1.f - x2;              // coefficient of w
    float n0  = ca * (-u0) + cb * w0;
    float n1  = ca * (-u1) + cb * w1;
    float nn  = warp_sum(n0 * n0 + n1 * n1);
    float den = fmaxf(1.f + 2.f * xy + x2 * y2, PB_EPS);
    float arg = sqrtf(nn) / den;
    return 2.f * atanh_fast(fminf(arg, PB_BND));
}

__global__ __launch_bounds__(256, 1)
void pb_fused_kernel(const float* __restrict__ encoded,
                     const float* __restrict__ n_encoded,
                     const float* __restrict__ mask1,
                     const float* __restrict__ mask2,
                     const float* __restrict__ mask_neg,
                     const float* __restrict__ W,
                     float* __restrict__ out)
{
    const int b    = blockIdx.x;
    const int tid  = threadIdx.x;
    const int wid  = tid >> 5;
    const int lane = tid & 31;

    __shared__ int   s_pos[6];
    __shared__ float s_mn[8][6];       // per-warp ||mx||^2 partials
    __shared__ float mxs[6][PB_D];     // final mobius vectors
    __shared__ float s_term[6];        // e_neg0..3, e_pos, angle
    __shared__ int   s_last;

    // ---- 1. one-hot position lookup (S = 256 = blockDim) ----
    if (mask1[(size_t)b * PB_S + tid] > 0.5f) s_pos[0] = tid;
    if (mask2[(size_t)b * PB_S + tid] > 0.5f) s_pos[1] = tid;
#pragma unroll
    for (int k = 0; k < PB_NEG; k++)
        if (mask_neg[(size_t)(b * PB_NEG + k) * PB_S + tid] > 0.5f)
            s_pos[2 + k] = tid;
    __syncthreads();

    // x row pointers (16B units), streamed straight from global
    const ulonglong2* xu[6];
    xu[0] = (const ulonglong2*)(encoded + ((size_t)b * PB_S + s_pos[0]) * PB_H);
    xu[1] = (const ulonglong2*)(encoded + ((size_t)b * PB_S + s_pos[1]) * PB_H);
#pragma unroll
    for (int k = 0; k < PB_NEG; k++)
        xu[2 + k] = (const ulonglong2*)(n_encoded +
                    ((size_t)(b * PB_NEG + k) * PB_S + s_pos[2 + k]) * PB_H);
    const ulonglong2* Wu = (const ulonglong2*)W;

    float rr[8][6];          // this warp's 8 output dims x 6 vectors (scaled)
    float sc[6], xnv[6];     // expmap0 scale, clip(||y||,EPS) — warp-local

    // ---- 2. matvec in 4 passes of 2 dims; pass 0 fuses sum-of-squares ----
#pragma unroll
    for (int p = 0; p < 4; p++) {
        const int dbase = wid * 8 + p * 2;
        u64 acc[2][6], ssa[6];
#pragma unroll
        for (int dd = 0; dd < 2; dd++)
#pragma unroll
            for (int j = 0; j < 6; j++) acc[dd][j] = 0ull;
        if (p == 0) {
#pragma unroll
            for (int j = 0; j < 6; j++) ssa[j] = 0ull;
        }

#pragma unroll
        for (int i = 0; i < 6; i++) {
            const int c = lane + i * 32;
            ulonglong2 xv[6];
#pragma unroll
            for (int j = 0; j < 6; j++) xv[j] = xu[j][c];          // LDG.128
            if (p == 0) {
#pragma unroll
                for (int j = 0; j < 6; j++) {
                    fma_x2(ssa[j], xv[j].x, xv[j].x, ssa[j]);      // x.x fused
                    fma_x2(ssa[j], xv[j].y, xv[j].y, ssa[j]);
                }
            }
#pragma unroll
            for (int dd = 0; dd < 2; dd++) {
                ulonglong2 wv = Wu[(size_t)(dbase + dd) * PB_H16 + c];  // LDG.128
#pragma unroll
                for (int j = 0; j < 6; j++) {
                    fma_x2(acc[dd][j], wv.x, xv[j].x, acc[dd][j]);
                    fma_x2(acc[dd][j], wv.y, xv[j].y, acc[dd][j]);
                }
            }
        }

        if (p == 0) {
            // expmap0 scales, warp-local (no barrier)
#pragma unroll
            for (int j = 0; j < 6; j++) {
                float ss  = warp_sum(x2_hsum(ssa[j]));
                float nrm = sqrtf(ss);
                float ncl = fmaxf(nrm, PB_EPS);
                sc[j]  = tanhf(ncl) / ncl;
                xnv[j] = fmaxf(sc[j] * nrm, PB_EPS);
            }
        }
#pragma unroll
        for (int dd = 0; dd < 2; dd++)
#pragma unroll
            for (int j = 0; j < 6; j++)
                rr[p * 2 + dd][j] = warp_sum(x2_hsum(acc[dd][j])) * sc[j];
    }

    // ---- 3. ||mx||^2 partials across warps (single data barrier) ----
    {
        float pm[6] = {0.f, 0.f, 0.f, 0.f, 0.f, 0.f};
#pragma unroll
        for (int k = 0; k < 8; k++)
#pragma unroll
            for (int j = 0; j < 6; j++) pm[j] += rr[k][j] * rr[k][j];
        if (lane == 0) {
#pragma unroll
            for (int j = 0; j < 6; j++) s_mn[wid][j] = pm[j];
        }
    }
    __syncthreads();

    // ---- 4. mobius rescale + publish this warp's 8 dims to smem ----
    {
#pragma unroll
        for (int j = 0; j < 6; j++) {
            float t = 0.f;
#pragma unroll
            for (int w = 0; w < 8; w++) t += s_mn[w][j];
            float mn  = fmaxf(sqrtf(t), PB_EPS);
            float fac = tanhf(mn / xnv[j] * atanh_fast(fminf(xnv[j], PB_BND))) / mn;
            float v = rr[0][j];
#pragma unroll
            for (int k = 1; k < 8; k++) v = (lane == k) ? rr[k][j] : v;
            if (lane < 8)
                mxs[j][wid * 8 + lane] = v * fac;
        }
    }
    __syncthreads();

    // ---- 5. epilogue: 6 warps compute angle + 5 distances in parallel ----
    if (wid < 6) {
        float u0  = mxs[0][lane];
        float u1  = mxs[0][lane + 32];
        float nu2 = warp_sum(u0 * u0 + u1 * u1);

        if (wid < 4) {                      // negative distances
            float w0 = mxs[2 + wid][lane];
            float w1 = mxs[2 + wid][lane + 32];
            float y2 = warp_sum(w0 * w0 + w1 * w1);
            float dn = warp_sum(u0 * w0 + u1 * w1);
            float dk = pb_dist(u0, u1, w0, w1, nu2, y2, dn);
            if (lane == 0) s_term[wid] = __expf(-dk);
        } else if (wid == 4) {              // positive-pair distance
            float v0  = mxs[1][lane];
            float v1  = mxs[1][lane + 32];
            float nv2 = warp_sum(v0 * v0 + v1 * v1);
            float duv = warp_sum(u0 * v0 + u1 * v1);
            float dp  = pb_dist(u0, u1, v0, v1, nu2, nv2, duv);
            if (lane == 0) s_term[4] = __expf(-dp);
        } else {                            // wid == 5: angle term
            float v0  = mxs[1][lane];
            float v1  = mxs[1][lane + 32];
            float nv2 = warp_sum(v0 * v0 + v1 * v1);
            float duv = warp_sum(u0 * v0 + u1 * v1);
            float d0  = u0 - v0, d1 = u1 - v1;
            float e2  = warp_sum(d0 * d0 + d1 * d1);
            float norm_v = sqrtf(nv2);
            float euclid = sqrtf(e2);
            float rad = fmaxf(1.f + nu2 * nv2 - 2.f * duv, PB_EPS);
            float den = fmaxf(norm_v * euclid * sqrtf(rad), PB_EPS);
            float ca  = (duv * (1.f + nv2) - nv2 * (1.f + nu2)) / den;
            ca = fminf(fmaxf(ca, -PB_BND), PB_BND);
            if (lane == 0) s_term[5] = acosf(ca);
        }
    }
    __syncthreads();

    // ---- 6. per-batch loss -> g_part; last block reduces mean into out ----
    if (tid == 0) {
        float Z1 = s_term[0] + s_term[1] + s_term[2] + s_term[3];
        float ep = s_term[4];
        float ns = __logf((Z1 + ep) / ep);  // == -log(ep/(Z1+ep))
        g_part[b] = s_term[5] + ns;
        __threadfence();
        unsigned t = atomicAdd(&g_cnt, 1u);
        s_last = (t == PB_B - 1u);
    }
    __syncthreads();

    if (s_last && wid == 0) {
        float v = __ldcg(&g_part[lane]) + __ldcg(&g_part[lane + 32]);
        v = warp_sum(v);
        if (lane == 0) {
            out[0] = v * (1.0f / PB_B);
            g_cnt = 0;                      // reset for next graph replay
        }
    }
}

extern "C" void kernel_launch(void* const* d_in, const int* in_sizes, int n_in,
                              void* d_out, int out_size)
{
    const float* encoded   = (const float*)d_in[0];
    const float* n_encoded = (const float*)d_in[1];
    const float* mask1     = (const float*)d_in[2];
    const float* mask2     = (const float*)d_in[3];
    const float* mask_neg  = (const float*)d_in[4];
    const float* W         = (const float*)d_in[5];
    float* out = (float*)d_out;

    pb_fused_kernel<<<PB_B, 256>>>(encoded, n_encoded,
                                   mask1, mask2, mask_neg, W, out);
}